// round 13
// baseline (speedup 1.0000x reference)
#include <cuda_runtime.h>

#define NB 16
#define NC 64
#define HW 65536
#define NBINS 256

// ---- scratch (no allocations allowed) ----
__device__ float         d_sum[NB * NC];        // raw plane sums
__device__ unsigned int  d_hist[NB * NBINS];
__device__ float         d_scale[NB * NBINS];
__device__ unsigned char d_q[NB * HW];
__device__ unsigned int  d_cnt[NB];             // cos-block arrivals per batch

// ============================================================
// Init each replay: zero hists + counters. grid=NB, 256 thr
// ============================================================
__global__ void k_init() {
    d_hist[blockIdx.x * NBINS + threadIdx.x] = 0u;
    if (threadIdx.x == 0) d_cnt[blockIdx.x] = 0u;
}

// ============================================================
// Pass 1: plane sums. grid = NB*NC blocks (ascending batches).
// ============================================================
__global__ void __launch_bounds__(256) k_mean(const float* __restrict__ F) {
    const int plane = blockIdx.x;                 // b*NC + c, ascending b
    const int tid = threadIdx.x;
    const float4* p = (const float4*)F + ((size_t)plane << 14);
    float s = 0.f;
    #pragma unroll 8
    for (int j = 0; j < 64; ++j) {                // 16384 float4 / 256 thr
        float4 v = __ldcg(p + j * 256 + tid);     // fill L2, skip L1
        s += (v.x + v.y) + (v.z + v.w);
    }
    __shared__ float red[256];
    red[tid] = s;
    __syncthreads();
    for (int o = 128; o > 0; o >>= 1) {
        if (tid < o) red[tid] += red[tid + o];
        __syncthreads();
    }
    if (tid == 0) d_sum[plane] = red[0];
}

// ============================================================
// Pass 2: a-hat (per block) + cosine + quantize + hist; the
// last-finishing block per batch builds the LUT in its tail.
// grid = NB*64 blocks; REVERSED batch order (eat L2 leftovers).
// ============================================================
__global__ void __launch_bounds__(256) k_cos(const float* __restrict__ F) {
    const int tid = threadIdx.x;
    const int b   = (NB - 1) - (blockIdx.x >> 6);   // early blocks -> high batches
    const int blk = blockIdx.x & 63;

    __shared__ float        sA[NC];
    __shared__ float        sR[NBINS];            // reduce / cdf scratch
    __shared__ float        sT[NBINS];            // scan tmp
    __shared__ unsigned int sU[NBINS];
    __shared__ int          sLast;

    // ---- a-hat (fused prep) ----
    sU[tid] = 0u;
    sR[tid] = 0.f;
    if (tid < NC) {
        float a = d_sum[b * NC + tid] * (1.0f / HW);
        sA[tid] = a;
        sR[tid] = a * a;
    }
    __syncthreads();
    for (int o = 128; o > 0; o >>= 1) {
        if (tid < o) sR[tid] += sR[tid + o];
        __syncthreads();
    }
    const float inv = 1.0f / fmaxf(sqrtf(sR[0]), 1e-12f);
    __syncthreads();
    if (tid < NC) sA[tid] *= inv;
    __syncthreads();

    // ---- cosine: each thread owns one float4-pixel, loops 64 channels ----
    const int p4 = (blk << 8) + tid;              // [0, 16384)
    const float4* fp = (const float4*)F + ((size_t)b << 20) + p4;
    float d0 = 0.f, d1 = 0.f, d2 = 0.f, d3 = 0.f;
    float s0 = 0.f, s1 = 0.f, s2 = 0.f, s3 = 0.f;
    #pragma unroll 8
    for (int c = 0; c < NC; ++c) {
        float4 v = fp[(size_t)c << 14];
        float ac = sA[c];
        d0 += ac * v.x; d1 += ac * v.y; d2 += ac * v.z; d3 += ac * v.w;
        s0 += v.x * v.x; s1 += v.y * v.y; s2 += v.z * v.z; s3 += v.w * v.w;
    }
    int q0 = ((int)((d0 / fmaxf(sqrtf(s0), 1e-12f)) * 255.0f)) & 255;
    int q1 = ((int)((d1 / fmaxf(sqrtf(s1), 1e-12f)) * 255.0f)) & 255;
    int q2 = ((int)((d2 / fmaxf(sqrtf(s2), 1e-12f)) * 255.0f)) & 255;
    int q3 = ((int)((d3 / fmaxf(sqrtf(s3), 1e-12f)) * 255.0f)) & 255;

    atomicAdd(&sU[q0], 1u); atomicAdd(&sU[q1], 1u);
    atomicAdd(&sU[q2], 1u); atomicAdd(&sU[q3], 1u);

    *(uchar4*)(d_q + ((size_t)b << 16) + ((size_t)p4 << 2)) =
        make_uchar4((unsigned char)q0, (unsigned char)q1,
                    (unsigned char)q2, (unsigned char)q3);

    __syncthreads();
    unsigned int cnt = sU[tid];
    if (cnt) atomicAdd(&d_hist[b * NBINS + tid], cnt);
    __syncthreads();

    if (tid == 0) {
        __threadfence();
        sLast = (atomicAdd(&d_cnt[b], 1u) == 63u);
    }
    __syncthreads();

    if (sLast) {                                  // last block of batch: LUT
        __threadfence();
        float h = (float)d_hist[b * NBINS + tid];
        sR[tid] = h;
        __syncthreads();
        for (int o = 1; o < NBINS; o <<= 1) {     // inclusive scan
            float v = sR[tid];
            float add = (tid >= o) ? sR[tid - o] : 0.f;
            __syncthreads();
            sR[tid] = v + add;
            __syncthreads();
        }
        sT[tid] = (h > 0.f) ? sR[tid] : (float)(HW + 1);
        __syncthreads();
        for (int o = 128; o > 0; o >>= 1) {
            if (tid < o) sT[tid] = fminf(sT[tid], sT[tid + o]);
            __syncthreads();
        }
        float cmin  = sT[0];
        float denom = fmaxf((float)HW - cmin, 1.0f);
        float lut   = rintf((sR[tid] - cmin) * (255.0f / denom));
        lut = fminf(fmaxf(lut, 0.0f), 255.0f);
        d_scale[b * NBINS + tid] = lut * (1.0f / 255.0f);
    }
}

// ============================================================
// Pass 3: pixel-stationary multiply with hoisted scale.
// grid = NB*64 blocks (ascending: eats k_cos's L2 leftovers).
// ============================================================
__global__ void __launch_bounds__(256) k_mul(const float* __restrict__ F,
                                             float* __restrict__ out) {
    const int tid = threadIdx.x;
    const int b   = blockIdx.x >> 6;
    const int blk = blockIdx.x & 63;
    const int p4  = (blk << 8) + tid;             // this thread's float4-pixel

    uchar4 qv = *(const uchar4*)(d_q + ((size_t)b << 16) + ((size_t)p4 << 2));
    const float* sc = d_scale + b * NBINS;        // 1 KB, L2-hot
    const float sx = __ldg(sc + qv.x), sy = __ldg(sc + qv.y);
    const float sz = __ldg(sc + qv.z), sw = __ldg(sc + qv.w);

    const float4* Fb = (const float4*)F + ((size_t)b << 20) + p4;
    float4*       Ob = (float4*)out + ((size_t)b << 20) + p4;
    #pragma unroll 8
    for (int c = 0; c < NC; ++c) {
        float4 v = __ldcs(Fb + ((size_t)c << 14));   // last use: evict-first
        float4 o;
        o.x = v.x * sx;
        o.y = v.y * sy;
        o.z = v.z * sz;
        o.w = v.w * sw;
        __stcs(Ob + ((size_t)c << 14), o);           // streaming store
    }
}

// ============================================================
extern "C" void kernel_launch(void* const* d_in, const int* in_sizes, int n_in,
                              void* d_out, int out_size) {
    const float* F = (const float*)d_in[0];
    float* out = (float*)d_out;
    (void)in_sizes; (void)n_in; (void)out_size;

    k_init<<<NB, NBINS>>>();
    k_mean<<<NB * NC, 256>>>(F);
    k_cos<<<NB * 64, 256>>>(F);
    k_mul<<<NB * 64, 256>>>(F, out);
}

// round 14
// speedup vs baseline: 1.1223x; 1.1223x over previous
#include <cuda_runtime.h>

#define NB 16
#define NC 64
#define HW 65536
#define NBINS 256
#define NBLK 512
#define NA  64      // stage A (mean) blocks: 1 per plane
#define NBB 128     // stage B (cos/hist/LUT) blocks
#define NCC 320     // stage C (mul) blocks; stride 320*256 = 5*16384 -> p4 invariant

// ---- scratch (no allocations allowed) ----
__device__ float         d_sum[NB * NC];        // raw plane sums
__device__ unsigned int  d_hist[NB * NBINS];
__device__ float         d_scale[NB * NBINS];
__device__ unsigned char d_q[NB * HW];
__device__ unsigned int  d_cA[NB];              // A arrivals (==64: sums ready)
__device__ unsigned int  d_cB[NB];              // B arrivals (==129: LUT ready)
__device__ unsigned int  d_cC[NB];              // C arrivals (==320: batch written)

__global__ void k_init() {
    d_hist[blockIdx.x * NBINS + threadIdx.x] = 0u;
    if (threadIdx.x == 0) {
        d_cA[blockIdx.x] = 0u; d_cB[blockIdx.x] = 0u; d_cC[blockIdx.x] = 0u;
    }
}

// Busy-poll (NO nanosleep — wakeup latency is the pipeline's bottleneck).
// Only one thread per block spins, so issue-slot cost is negligible.
__device__ __forceinline__ void spin_ge(const unsigned int* p, unsigned int v) {
    const volatile unsigned int* vp = (const volatile unsigned int*)p;
    while (*vp < v) { }
}

// ============================================================
// Persistent 3-stage pipeline over batches.
//   A (64):  DRAM read b+k, plane sums (fills L2)
//   B (128): L2 read, cos/quant/hist/LUT
//   C (320): pure stream out = F * s (per-thread scale hoisted)
// ============================================================
__global__ void __launch_bounds__(256, 4) k_pipe(const float* __restrict__ F,
                                                 float* __restrict__ out) {
    const int tid = threadIdx.x;
    const int bid = blockIdx.x;

    __shared__ float        sPart[8 * 256];
    __shared__ float        sA[NBINS];
    __shared__ unsigned int sU[NBINS];
    __shared__ int          sLast;

    if (bid < NA) {
        // ================= Stage A: plane sums (DRAM -> L2 fill) ==============
        const int c = bid;
        for (int b = 0; b < NB; ++b) {
            if (b >= 3) {                        // keep <=4 slabs (64 MB) in L2
                if (tid == 0) spin_ge(&d_cC[b - 3], NCC);
                __syncthreads();
            }
            const float4* base = (const float4*)F + ((size_t)(b * NC + c) << 14);
            float s = 0.f;
            #pragma unroll 8
            for (int j = 0; j < 64; ++j) {       // 16384 float4 / 256 thr
                float4 v = __ldcg(base + j * 256 + tid);   // fill L2, skip L1
                s += (v.x + v.y) + (v.z + v.w);
            }
            sPart[tid] = s;
            __syncthreads();
            for (int o = 128; o > 0; o >>= 1) {
                if (tid < o) sPart[tid] += sPart[tid + o];
                __syncthreads();
            }
            if (tid == 0) {
                d_sum[b * NC + c] = sPart[0];
                __threadfence();
                atomicAdd(&d_cA[b], 1u);
            }
            __syncthreads();                     // sPart reused next batch
        }
    } else if (bid < NA + NBB) {
        // ================= Stage B: cosine + quantize + hist + LUT ============
        const int sub = bid - NA;
        for (int b = 0; b < NB; ++b) {
            if (tid == 0) spin_ge(&d_cA[b], NA);
            __syncthreads();
            __threadfence();

            // a-hat
            if (tid < NC) sA[tid] = d_sum[b * NC + tid] * (1.0f / HW);
            sU[tid] = 0u;
            __syncthreads();
            sPart[tid] = (tid < NC) ? sA[tid] * sA[tid] : 0.f;
            __syncthreads();
            for (int o = 128; o > 0; o >>= 1) {
                if (tid < o) sPart[tid] += sPart[tid + o];
                __syncthreads();
            }
            const float inv = 1.0f / fmaxf(sqrtf(sPart[0]), 1e-12f);
            __syncthreads();
            if (tid < NC) sA[tid] *= inv;
            __syncthreads();

            // cosine for 128 float4-pixels, channels split across thread halves
            const int px = (sub << 7) + (tid & 127);
            const int c0 = (tid >> 7) << 5;
            const float4* fp = (const float4*)F + ((size_t)b << 20) + px;
            float d0 = 0.f, d1 = 0.f, d2 = 0.f, d3 = 0.f;
            float s0 = 0.f, s1 = 0.f, s2 = 0.f, s3 = 0.f;
            #pragma unroll 8
            for (int i = 0; i < 32; ++i) {
                float4 v = fp[(size_t)(c0 + i) << 14];
                float ac = sA[c0 + i];
                d0 += ac * v.x; d1 += ac * v.y; d2 += ac * v.z; d3 += ac * v.w;
                s0 += v.x * v.x; s1 += v.y * v.y; s2 += v.z * v.z; s3 += v.w * v.w;
            }
            sPart[0 * 256 + tid] = d0; sPart[1 * 256 + tid] = d1;
            sPart[2 * 256 + tid] = d2; sPart[3 * 256 + tid] = d3;
            sPart[4 * 256 + tid] = s0; sPart[5 * 256 + tid] = s1;
            sPart[6 * 256 + tid] = s2; sPart[7 * 256 + tid] = s3;
            __syncthreads();

            if (tid < 128) {
                float D0 = sPart[0 * 256 + tid] + sPart[0 * 256 + tid + 128];
                float D1 = sPart[1 * 256 + tid] + sPart[1 * 256 + tid + 128];
                float D2 = sPart[2 * 256 + tid] + sPart[2 * 256 + tid + 128];
                float D3 = sPart[3 * 256 + tid] + sPart[3 * 256 + tid + 128];
                float S0 = sPart[4 * 256 + tid] + sPart[4 * 256 + tid + 128];
                float S1 = sPart[5 * 256 + tid] + sPart[5 * 256 + tid + 128];
                float S2 = sPart[6 * 256 + tid] + sPart[6 * 256 + tid + 128];
                float S3 = sPart[7 * 256 + tid] + sPart[7 * 256 + tid + 128];
                int q0 = ((int)((D0 / fmaxf(sqrtf(S0), 1e-12f)) * 255.0f)) & 255;
                int q1 = ((int)((D1 / fmaxf(sqrtf(S1), 1e-12f)) * 255.0f)) & 255;
                int q2 = ((int)((D2 / fmaxf(sqrtf(S2), 1e-12f)) * 255.0f)) & 255;
                int q3 = ((int)((D3 / fmaxf(sqrtf(S3), 1e-12f)) * 255.0f)) & 255;
                atomicAdd(&sU[q0], 1u); atomicAdd(&sU[q1], 1u);
                atomicAdd(&sU[q2], 1u); atomicAdd(&sU[q3], 1u);
                const int mypx = (sub << 7) + tid;
                *(uchar4*)(d_q + ((size_t)b << 16) + ((size_t)mypx << 2)) =
                    make_uchar4((unsigned char)q0, (unsigned char)q1,
                                (unsigned char)q2, (unsigned char)q3);
            }
            __syncthreads();
            unsigned int cnt = sU[tid];
            if (cnt) atomicAdd(&d_hist[b * NBINS + tid], cnt);
            __syncthreads();

            if (tid == 0) {
                __threadfence();
                unsigned int old = atomicAdd(&d_cB[b], 1u);
                sLast = (old == NBB - 1);
            }
            __syncthreads();

            if (sLast) {                         // last B block builds the LUT
                __threadfence();
                float h = (float)d_hist[b * NBINS + tid];
                float* cdf = sPart;
                float* tmp = sPart + 256;
                cdf[tid] = h;
                __syncthreads();
                for (int o = 1; o < NBINS; o <<= 1) {
                    float v = cdf[tid];
                    float add = (tid >= o) ? cdf[tid - o] : 0.f;
                    __syncthreads();
                    cdf[tid] = v + add;
                    __syncthreads();
                }
                tmp[tid] = (h > 0.f) ? cdf[tid] : (float)(HW + 1);
                __syncthreads();
                for (int o = 128; o > 0; o >>= 1) {
                    if (tid < o) tmp[tid] = fminf(tmp[tid], tmp[tid + o]);
                    __syncthreads();
                }
                float cmin  = tmp[0];
                float denom = fmaxf((float)HW - cmin, 1.0f);
                float lut   = rintf((cdf[tid] - cmin) * (255.0f / denom));
                lut = fminf(fmaxf(lut, 0.0f), 255.0f);
                d_scale[b * NBINS + tid] = lut * (1.0f / 255.0f);
                __syncthreads();
                if (tid == 0) {
                    __threadfence();
                    atomicAdd(&d_cB[b], 1u);     // -> 129 : LUT ready
                }
            }
            __syncthreads();
        }
    } else {
        // ========== Stage C: pure stream (per-thread scale hoisted) ===========
        const int sub = bid - NA - NBB;
        const int idx0 = (sub << 8) + tid;       // < 81920
        const int p4   = idx0 & 16383;           // invariant: stride % 16384 == 0
        for (int b = 0; b < NB; ++b) {
            if (tid == 0) spin_ge(&d_cB[b], NBB + 1);
            __syncthreads();
            __threadfence();

            // hoisted per-thread scale vector (constant across all 64 planes)
            uchar4 qv = *(const uchar4*)(d_q + ((size_t)b << 16) + ((size_t)p4 << 2));
            const float* sc = d_scale + b * NBINS;       // 1 KB, L2-hot
            const float sx = __ldg(sc + qv.x), sy = __ldg(sc + qv.y);
            const float sz = __ldg(sc + qv.z), sw = __ldg(sc + qv.w);

            const float4* Fb = (const float4*)F + ((size_t)b << 20);
            float4*       Ob = (float4*)out + ((size_t)b << 20);
            #pragma unroll 4
            for (int idx = idx0; idx < (1 << 20); idx += NCC * 256) {
                float4 v = __ldcs(Fb + idx);     // last use: evict-first
                float4 o;
                o.x = v.x * sx;
                o.y = v.y * sy;
                o.z = v.z * sz;
                o.w = v.w * sw;
                __stcs(Ob + idx, o);             // streaming store
            }
            if (tid == 0) {
                __threadfence();
                atomicAdd(&d_cC[b], 1u);
            }
            __syncthreads();
        }
    }
}

// ============================================================
extern "C" void kernel_launch(void* const* d_in, const int* in_sizes, int n_in,
                              void* d_out, int out_size) {
    const float* F = (const float*)d_in[0];
    float* out = (float*)d_out;
    (void)in_sizes; (void)n_in; (void)out_size;

    k_init<<<NB, NBINS>>>();
    k_pipe<<<NBLK, 256>>>(F, out);
}